// round 6
// baseline (speedup 1.0000x reference)
#include <cuda_runtime.h>
#include <cuda_fp16.h>
#include <cstdint>

#define TOKENS   64
#define IN_F     4096
#define OUT_F    16384
#define TILE_M   128
#define KC       64
#define NCHUNK   (IN_F / KC)   // 64
#define NTHREADS 256

// ---- shared memory map (dynamic) ----
// A tiles (W fp16): 2 x (128 rows x 128 B) ; X tiles: 2 x (64 rows x 128 B)
#define SM_A0    0
#define SM_A1    16384
#define SM_X0    32768
#define SM_X1    (32768 + 8192)
#define SM_TOTAL 49152

// dtype-resolution flag: 1 if fp16 tensors were upcast to fp32 by the harness
__device__ int g_x_is_f32;

__global__ void sniff_kernel(const unsigned int* xbits) {
    if (threadIdx.x == 0) {
        int c = 0;
        #pragma unroll 1
        for (int i = 0; i < 256; ++i)
            if ((xbits[i] & 0x1FFFu) == 0u) ++c;   // fp16->fp32 upcast: low 13 mantissa bits zero
        g_x_is_f32 = (c > 192) ? 1 : 0;
    }
}

__device__ __forceinline__ uint32_t smem_u32(const void* p) {
    uint32_t a;
    asm("{ .reg .u64 t; cvta.to.shared.u64 t, %1; cvt.u32.u64 %0, t; }" : "=r"(a) : "l"(p));
    return a;
}

__device__ __forceinline__ uint32_t pack_i2h2(int a, int b) {
    __half2 h = __halves2half2(__int2half_rn(a), __int2half_rn(b));
    return *reinterpret_cast<uint32_t*>(&h);
}

__device__ __forceinline__ uint32_t pack_f2h2(float a, float b) {
    __half2 h = __floats2half2_rn(a, b);
    return *reinterpret_cast<uint32_t*>(&h);
}

#define LDSM_X4(r0, r1, r2, r3, addr)                                            \
    asm volatile("ldmatrix.sync.aligned.m8n8.x4.shared.b16 {%0,%1,%2,%3}, [%4];" \
                 : "=r"(r0), "=r"(r1), "=r"(r2), "=r"(r3) : "r"(addr))

#define MMA16816(d, a, b0, b1)                                               \
    asm volatile("mma.sync.aligned.m16n8k16.row.col.f32.f16.f16.f32 "        \
                 "{%0,%1,%2,%3}, {%4,%5,%6,%7}, {%8,%9}, {%0,%1,%2,%3};"     \
                 : "+f"((d)[0]), "+f"((d)[1]), "+f"((d)[2]), "+f"((d)[3])    \
                 : "r"((a)[0]), "r"((a)[1]), "r"((a)[2]), "r"((a)[3]),       \
                   "r"(b0), "r"(b1))

template <int XF32>
__global__ void __launch_bounds__(NTHREADS, 1)
w8a16_linear_kernel(const void* __restrict__ xin, const int* __restrict__ w,
                    const void* __restrict__ scin, const void* __restrict__ bin,
                    void* __restrict__ outv)
{
    if (g_x_is_f32 != XF32) return;   // only the matching dtype instantiation runs

    extern __shared__ __align__(1024) char smem[];
    const uint32_t sb  = smem_u32(smem);
    const int tid = threadIdx.x;
    const int wid = tid >> 5;
    const int lid = tid & 31;
    const int m0  = blockIdx.x * TILE_M;

    // ---- staging assignment ----
    // W chunk: 128 rows x 64 int32; thread does 8 int4 (one per 16-row pass)
    const int wrow = tid >> 4;          // 0..15 base row
    const int wc   = tid & 15;          // int4 column (4 k each)
    const int4* wg = reinterpret_cast<const int4*>(w + (size_t)(m0 + wrow) * IN_F) + wc;
    const uint32_t wsts0 = sb + (uint32_t)(wrow * 128) + (((uint32_t)(wc * 8)) ^ ((uint32_t)((wrow & 7) << 4)));

    // X chunk: 64 rows x 64 k; thread covers 8 k-values on rows xrow and xrow+32
    const int xrow = tid >> 3;          // 0..31 base row
    const int xc   = tid & 7;           // 8-k granule
    const uint32_t xsts0 = sb + (uint32_t)(xrow * 128) + (((uint32_t)(xc * 16)) ^ ((uint32_t)((xrow & 7) << 4)));

    const int4*   xg  = reinterpret_cast<const int4*>((const __half*)xin + (size_t)xrow * IN_F) + xc;      // fp16 path
    const float4* xg4 = reinterpret_cast<const float4*>((const float*)xin) + (size_t)xrow * (IN_F / 4) + xc * 2; // fp32 path

    // ---- MMA lane geometry (warps 0-3, each m32 x n64) ----
    const uint32_t lxor = (uint32_t)((lid & 7) << 4);
    const uint32_t arow = (uint32_t)(wid * 32 + (lid & 15));
    const uint32_t acol = (uint32_t)(((lid >> 4) & 1) * 16);
    const uint32_t brow = (uint32_t)((((lid >> 4) & 1) * 8) + (lid & 7));
    const uint32_t bcol = (uint32_t)(((lid >> 3) & 1) * 16);

    float acc[2][8][4];
    #pragma unroll
    for (int a = 0; a < 2; ++a)
        #pragma unroll
        for (int b = 0; b < 8; ++b)
            #pragma unroll
            for (int c = 0; c < 4; ++c) acc[a][b][c] = 0.0f;

    // ---- prefetch chunk 0 ----
    int4 wv[8];
    #pragma unroll
    for (int p = 0; p < 8; ++p) wv[p] = wg[p * 16 * (IN_F / 4)];
    int4   xv[2];
    float4 xf[4];
    if (XF32) {
        xf[0] = xg4[0];
        xf[1] = xg4[1];
        xf[2] = xg4[32 * (IN_F / 4)];
        xf[3] = xg4[32 * (IN_F / 4) + 1];
        xg4 += KC / 4;
    } else {
        xv[0] = xg[0];
        xv[1] = xg[32 * (IN_F / 8)];
        xg += KC / 8;
    }
    wg += KC / 4;

    #pragma unroll 1
    for (int k = 0; k < NCHUNK; ++k) {
        int4 wn[8];
        #pragma unroll
        for (int p = 0; p < 8; ++p) wn[p] = make_int4(0, 0, 0, 0);
        int4   xn[2] = {make_int4(0,0,0,0), make_int4(0,0,0,0)};
        float4 xnf[4] = {make_float4(0,0,0,0), make_float4(0,0,0,0),
                         make_float4(0,0,0,0), make_float4(0,0,0,0)};
        if (k + 1 < NCHUNK) {            // issue next chunk's LDGs early (cover DRAM latency)
            #pragma unroll
            for (int p = 0; p < 8; ++p) wn[p] = wg[p * 16 * (IN_F / 4)];
            if (XF32) {
                xnf[0] = xg4[0];
                xnf[1] = xg4[1];
                xnf[2] = xg4[32 * (IN_F / 4)];
                xnf[3] = xg4[32 * (IN_F / 4) + 1];
                xg4 += KC / 4;
            } else {
                xn[0] = xg[0];
                xn[1] = xg[32 * (IN_F / 8)];
                xg += KC / 8;
            }
            wg += KC / 4;
        }

        const uint32_t aoff = (k & 1) ? (uint32_t)SM_A1 : (uint32_t)SM_A0;
        const uint32_t xoff = (k & 1) ? (uint32_t)SM_X1 : (uint32_t)SM_X0;

        // convert + store W (int32 -> fp16, swizzled)
        #pragma unroll
        for (int p = 0; p < 8; ++p) {
            uint32_t h0 = pack_i2h2(wv[p].x, wv[p].y);
            uint32_t h1 = pack_i2h2(wv[p].z, wv[p].w);
            asm volatile("st.shared.v2.b32 [%0], {%1, %2};"
                         :: "r"(wsts0 + aoff + (uint32_t)(p * 2048)),
                            "r"(h0), "r"(h1) : "memory");
        }
        // store x tiles (convert if fp32)
        if (XF32) {
            uint32_t h0 = pack_f2h2(xf[0].x, xf[0].y), h1 = pack_f2h2(xf[0].z, xf[0].w);
            uint32_t h2 = pack_f2h2(xf[1].x, xf[1].y), h3 = pack_f2h2(xf[1].z, xf[1].w);
            asm volatile("st.shared.v4.b32 [%0], {%1, %2, %3, %4};"
                         :: "r"(xsts0 + xoff), "r"(h0), "r"(h1), "r"(h2), "r"(h3) : "memory");
            uint32_t h4 = pack_f2h2(xf[2].x, xf[2].y), h5 = pack_f2h2(xf[2].z, xf[2].w);
            uint32_t h6 = pack_f2h2(xf[3].x, xf[3].y), h7 = pack_f2h2(xf[3].z, xf[3].w);
            asm volatile("st.shared.v4.b32 [%0], {%1, %2, %3, %4};"
                         :: "r"(xsts0 + xoff + 4096u), "r"(h4), "r"(h5), "r"(h6), "r"(h7) : "memory");
        } else {
            asm volatile("st.shared.v4.b32 [%0], {%1, %2, %3, %4};"
                         :: "r"(xsts0 + xoff),
                            "r"((uint32_t)xv[0].x), "r"((uint32_t)xv[0].y),
                            "r"((uint32_t)xv[0].z), "r"((uint32_t)xv[0].w) : "memory");
            asm volatile("st.shared.v4.b32 [%0], {%1, %2, %3, %4};"
                         :: "r"(xsts0 + xoff + 4096u),
                            "r"((uint32_t)xv[1].x), "r"((uint32_t)xv[1].y),
                            "r"((uint32_t)xv[1].z), "r"((uint32_t)xv[1].w) : "memory");
        }

        __syncthreads();

        if (wid < 4) {
            const uint32_t abase = sb + aoff;
            const uint32_t xbase = sb + xoff;
            #pragma unroll
            for (int ks = 0; ks < 4; ++ks) {
                uint32_t af[2][4], bf[4][4];
                #pragma unroll
                for (int mt = 0; mt < 2; ++mt) {
                    uint32_t addr = abase + (arow + (uint32_t)(mt * 16)) * 128u
                                  + (((uint32_t)(ks * 32) + acol) ^ lxor);
                    LDSM_X4(af[mt][0], af[mt][1], af[mt][2], af[mt][3], addr);
                }
                #pragma unroll
                for (int tg = 0; tg < 4; ++tg) {
                    uint32_t addr = xbase + (brow + (uint32_t)(tg * 16)) * 128u
                                  + (((uint32_t)(ks * 32) + bcol) ^ lxor);
                    LDSM_X4(bf[tg][0], bf[tg][1], bf[tg][2], bf[tg][3], addr);
                }
                #pragma unroll
                for (int mt = 0; mt < 2; ++mt)
                    #pragma unroll
                    for (int tg = 0; tg < 4; ++tg) {
                        MMA16816(acc[mt][tg * 2],     af[mt], bf[tg][0], bf[tg][1]);
                        MMA16816(acc[mt][tg * 2 + 1], af[mt], bf[tg][2], bf[tg][3]);
                    }
            }
        }

        #pragma unroll
        for (int p = 0; p < 8; ++p) wv[p] = wn[p];
        if (XF32) { xf[0] = xnf[0]; xf[1] = xnf[1]; xf[2] = xnf[2]; xf[3] = xnf[3]; }
        else      { xv[0] = xn[0];  xv[1] = xn[1]; }
    }

    // ---- epilogue: scale + bias, write output ----
    if (wid < 4) {
        const int grp = lid >> 2;
        const int q   = lid & 3;
        #pragma unroll
        for (int mt = 0; mt < 2; ++mt) {
            const int mloc = wid * 32 + mt * 16 + grp;      // rows mloc and mloc+8
            float s0, s1, bb0, bb1;
            if (XF32) {
                s0  = ((const float*)scin)[m0 + mloc];
                bb0 = ((const float*)bin)[m0 + mloc];
                s1  = ((const float*)scin)[m0 + mloc + 8];
                bb1 = ((const float*)bin)[m0 + mloc + 8];
            } else {
                s0  = __half2float(((const __half*)scin)[m0 + mloc]);
                bb0 = __half2float(((const __half*)bin)[m0 + mloc]);
                s1  = __half2float(((const __half*)scin)[m0 + mloc + 8]);
                bb1 = __half2float(((const __half*)bin)[m0 + mloc + 8]);
            }
            #pragma unroll
            for (int nt = 0; nt < 8; ++nt) {
                const int t = nt * 8 + q * 2;
                const float v00 = acc[mt][nt][0] * s0 + bb0;
                const float v01 = acc[mt][nt][1] * s0 + bb0;
                const float v10 = acc[mt][nt][2] * s1 + bb1;
                const float v11 = acc[mt][nt][3] * s1 + bb1;
                const size_t i00 = (size_t)t * OUT_F + (m0 + mloc);
                const size_t i01 = (size_t)(t + 1) * OUT_F + (m0 + mloc);
                const size_t i10 = (size_t)t * OUT_F + (m0 + mloc + 8);
                const size_t i11 = (size_t)(t + 1) * OUT_F + (m0 + mloc + 8);
                if (XF32) {
                    ((float*)outv)[i00] = v00;
                    ((float*)outv)[i01] = v01;
                    ((float*)outv)[i10] = v10;
                    ((float*)outv)[i11] = v11;
                } else {
                    ((__half*)outv)[i00] = __float2half(v00);
                    ((__half*)outv)[i01] = __float2half(v01);
                    ((__half*)outv)[i10] = __float2half(v10);
                    ((__half*)outv)[i11] = __float2half(v11);
                }
            }
        }
    }
}

extern "C" void kernel_launch(void* const* d_in, const int* in_sizes, int n_in,
                              void* d_out, int out_size) {
    const void* x    = d_in[0];
    const int*  w    = (const int*)d_in[1];
    const void* sc   = d_in[2];
    const void* bias = d_in[3];

    cudaFuncSetAttribute(w8a16_linear_kernel<0>,
                         cudaFuncAttributeMaxDynamicSharedMemorySize, SM_TOTAL);
    cudaFuncSetAttribute(w8a16_linear_kernel<1>,
                         cudaFuncAttributeMaxDynamicSharedMemorySize, SM_TOTAL);

    sniff_kernel<<<1, 32>>>((const unsigned int*)x);
    w8a16_linear_kernel<1><<<OUT_F / TILE_M, NTHREADS, SM_TOTAL>>>(x, w, sc, bias, d_out);
    w8a16_linear_kernel<0><<<OUT_F / TILE_M, NTHREADS, SM_TOTAL>>>(x, w, sc, bias, d_out);
}